// round 1
// baseline (speedup 1.0000x reference)
#include <cuda_runtime.h>
#include <math.h>

// Problem constants
#define NB 4
#define NS 2048
#define ND 1024
#define NHD 64
#define NM (NB*NS)   // 8192

// ---------------- scratch (device globals; no allocation allowed) ----------
__device__ float g_Wqh[ND*NHD];     // Wq @ wq_h   [1024,64]
__device__ float g_Wkh[ND*NHD];
__device__ float g_Wvh[ND*NHD];
__device__ float g_Wored[NHD*ND];   // head-summed Wo [64,1024]
__device__ float g_qh[NM*NHD];      // per-head projections [8192,64]
__device__ float g_kh[NM*NHD];
__device__ float g_vh[NM*NHD];
__device__ float g_oh[NM*NHD];      // attention output [8192,64]

// ---------------- tiny kernels --------------------------------------------
__global__ void zero_wcomb_kernel() {
    int i = blockIdx.x*blockDim.x + threadIdx.x;
    if (i < ND*NHD) { g_Wqh[i]=0.f; g_Wkh[i]=0.f; g_Wvh[i]=0.f; }
}

// Wo_red[h,e] = sum_{j<16} Wo[(j*64+h), e]
__global__ void wored_kernel(const float* __restrict__ Wo) {
    int h = blockIdx.x;
    for (int e = threadIdx.x; e < ND; e += blockDim.x) {
        float s = 0.f;
        #pragma unroll
        for (int j = 0; j < 16; j++) s += Wo[(size_t)(j*NHD + h)*ND + e];
        g_Wored[h*ND + e] = s;
    }
}

// ---------------- shared GEMM core: C[M,*] 128x64 tile, BK=16 --------------
// 256 threads (tx=tid&15, ty=tid>>4), thread tile 8x4 on strided rows/cols.
// A read k-vectorized (float4), B transposed into smem. FMA-bound by design.
template<bool ATOMIC, bool BIAS>
__device__ __forceinline__ void gemm_core(
    const float* __restrict__ A, int lda,
    const float* __restrict__ Bm, int ldb,
    float* __restrict__ C, int ldc,
    const float* __restrict__ bias,
    int m0, int n0, int kStart, int kLen)
{
    __shared__ float As[128*20];   // [row][16 k + pad4]  (17 f4 stride -> bank-friendly)
    __shared__ float Bs[64*20];    // transposed: [n][16 k + pad4]
    int tid = threadIdx.x;
    int tx = tid & 15, ty = tid >> 4;

    float acc[8][4];
    #pragma unroll
    for (int i = 0; i < 8; i++)
        #pragma unroll
        for (int j = 0; j < 4; j++) acc[i][j] = 0.f;

    for (int kb = 0; kb < kLen; kb += 16) {
        int k0 = kStart + kb;
        // A tile: 128x16 floats = 512 f4, 2 per thread, coalesced
        #pragma unroll
        for (int p = 0; p < 2; p++) {
            int idx = tid + p*256;
            int r = idx >> 2, kc = idx & 3;
            float4 v = *(const float4*)(A + (size_t)(m0 + r)*lda + k0 + kc*4);
            *(float4*)(&As[r*20 + kc*4]) = v;
        }
        // B tile: 16x64 floats, load f4 along n, store transposed
        {
            int k = tid >> 4, nc = tid & 15;
            float4 v = *(const float4*)(Bm + (size_t)(k0 + k)*ldb + n0 + nc*4);
            Bs[(nc*4+0)*20 + k] = v.x;
            Bs[(nc*4+1)*20 + k] = v.y;
            Bs[(nc*4+2)*20 + k] = v.z;
            Bs[(nc*4+3)*20 + k] = v.w;
        }
        __syncthreads();
        #pragma unroll
        for (int kc = 0; kc < 4; kc++) {
            float4 a[8], b[4];
            #pragma unroll
            for (int i = 0; i < 8; i++)
                a[i] = *(const float4*)(&As[(ty + 16*i)*20 + kc*4]);  // broadcast
            #pragma unroll
            for (int j = 0; j < 4; j++)
                b[j] = *(const float4*)(&Bs[(tx + 16*j)*20 + kc*4]);  // <=2-way
            #pragma unroll
            for (int i = 0; i < 8; i++)
                #pragma unroll
                for (int j = 0; j < 4; j++) {
                    acc[i][j] = fmaf(a[i].x, b[j].x, acc[i][j]);
                    acc[i][j] = fmaf(a[i].y, b[j].y, acc[i][j]);
                    acc[i][j] = fmaf(a[i].z, b[j].z, acc[i][j]);
                    acc[i][j] = fmaf(a[i].w, b[j].w, acc[i][j]);
                }
        }
        __syncthreads();
    }
    #pragma unroll
    for (int i = 0; i < 8; i++) {
        int m = m0 + ty + 16*i;
        #pragma unroll
        for (int j = 0; j < 4; j++) {
            int n = n0 + tx + 16*j;
            float v = acc[i][j];
            if (BIAS)   v += bias[n - n0];
            if (ATOMIC) atomicAdd(&C[(size_t)m*ldc + n], v);
            else        C[(size_t)m*ldc + n] = v;
        }
    }
}

// Combined weights: Wxh = Wx @ wx_h, split-K(8 x 128) with atomic accumulate.
// grid (8, 1, 24): z -> {matrix 0..2} x {k-chunk 0..7}
__global__ void combine_kernel(
    const float* __restrict__ Wq, const float* __restrict__ Wk, const float* __restrict__ Wv,
    const float* __restrict__ wqh, const float* __restrict__ wkh, const float* __restrict__ wvh)
{
    int z = blockIdx.z;
    int which = z >> 3;
    int chunk = z & 7;
    const float* A  = (which==0) ? Wq  : (which==1) ? Wk  : Wv;
    const float* Bm = (which==0) ? wqh : (which==1) ? wkh : wvh;
    float*       C  = (which==0) ? g_Wqh : (which==1) ? g_Wkh : g_Wvh;
    gemm_core<true,false>(A, ND, Bm, NHD, C, NHD, nullptr,
                          blockIdx.x*128, 0, chunk*128, 128);
}

// Per-head projections: xh = X @ Wxh + b.  grid (64, 1, 3)
__global__ void proj_kernel(
    const float* __restrict__ q, const float* __restrict__ k, const float* __restrict__ v,
    const float* __restrict__ bq, const float* __restrict__ bk, const float* __restrict__ bv)
{
    int which = blockIdx.z;
    const float* A    = (which==0) ? q     : (which==1) ? k     : v;
    const float* W    = (which==0) ? g_Wqh : (which==1) ? g_Wkh : g_Wvh;
    const float* bias = (which==0) ? bq    : (which==1) ? bk    : bv;
    float*       C    = (which==0) ? g_qh  : (which==1) ? g_kh  : g_vh;
    gemm_core<false,true>(A, ND, W, NHD, C, NHD, bias, blockIdx.x*128, 0, 0, ND);
}

// Final: out = oh @ Wo_red.  grid (64, 16)
__global__ void outgemm_kernel(float* __restrict__ out) {
    gemm_core<false,false>(g_oh, NHD, g_Wored, ND, out, ND, nullptr,
                           blockIdx.x*128, blockIdx.y*64, 0, NHD);
}

// ---------------- causal flash attention, single head, HD=64 ---------------
// BM=32 query rows per CTA, BN=64 keys per iter, 128 threads (tx 0..15, ty 0..7),
// 4x4 register tiles for both S and O. grid (64 qtiles, 4 batches),
// largest CTAs launched first (qb = 63 - bx) to fight triangular imbalance.
__global__ void attn_kernel() {
    __shared__ float Qs[32*68];   // [row][64 hd + pad4]  (f4-aligned, odd f4 stride)
    __shared__ float KPs[64*68];  // K tile; reused as P^T [key][32 rows] (stride 33)
    __shared__ float Vs[64*64];   // [key][hd]

    int tid = threadIdx.x;
    int tx = tid & 15, ty = tid >> 4;       // ty 0..7
    int qb = 63 - (int)blockIdx.x;
    int b  = blockIdx.y;
    size_t base = (size_t)b * NS * NHD;
    int r0 = qb * 32;

    // load Q tile 32x64
    #pragma unroll
    for (int p = 0; p < 4; p++) {
        int idx = tid + p*128;
        int r = idx >> 4, hc = idx & 15;
        float4 v = *(const float4*)(&g_qh[base + (size_t)(r0 + r)*NHD + hc*4]);
        *(float4*)(&Qs[r*68 + hc*4]) = v;
    }

    float m_r[4], l_r[4], o_r[4][4];
    #pragma unroll
    for (int i = 0; i < 4; i++) {
        m_r[i] = -1e30f; l_r[i] = 0.f;
        #pragma unroll
        for (int j = 0; j < 4; j++) o_r[i][j] = 0.f;
    }
    const float c1 = 0.125f * 1.4426950408889634f;   // (1/sqrt(64)) * log2(e)
    int nkt = (qb >> 1) + 1;   // causal: key tiles needed

    for (int jt = 0; jt < nkt; jt++) {
        __syncthreads();   // prev-iter PV reads of KPs/Vs must finish
        // load K, V tiles 64x64 each
        #pragma unroll
        for (int p = 0; p < 8; p++) {
            int idx = tid + p*128;
            int r = idx >> 4, hc = idx & 15;
            size_t g = base + (size_t)(jt*64 + r)*NHD + hc*4;
            float4 kv = *(const float4*)(&g_kh[g]);
            *(float4*)(&KPs[r*68 + hc*4]) = kv;
            float4 vv = *(const float4*)(&g_vh[g]);
            *(float4*)(&Vs[r*64 + hc*4]) = vv;
        }
        __syncthreads();

        // S = Q K^T, k-vectorized over hd
        float s[4][4];
        #pragma unroll
        for (int i = 0; i < 4; i++)
            #pragma unroll
            for (int j = 0; j < 4; j++) s[i][j] = 0.f;
        #pragma unroll
        for (int hc = 0; hc < 16; hc++) {
            float4 a[4], bb[4];
            #pragma unroll
            for (int i = 0; i < 4; i++)
                a[i] = *(const float4*)(&Qs[(ty + 8*i)*68 + hc*4]);    // broadcast
            #pragma unroll
            for (int j = 0; j < 4; j++)
                bb[j] = *(const float4*)(&KPs[(tx + 16*j)*68 + hc*4]); // <=2-way
            #pragma unroll
            for (int i = 0; i < 4; i++)
                #pragma unroll
                for (int j = 0; j < 4; j++) {
                    s[i][j] = fmaf(a[i].x, bb[j].x, s[i][j]);
                    s[i][j] = fmaf(a[i].y, bb[j].y, s[i][j]);
                    s[i][j] = fmaf(a[i].z, bb[j].z, s[i][j]);
                    s[i][j] = fmaf(a[i].w, bb[j].w, s[i][j]);
                }
        }

        // scale to log2 domain + causal mask (only the diagonal-straddling tile)
        bool last = (jt == nkt - 1);
        #pragma unroll
        for (int i = 0; i < 4; i++)
            #pragma unroll
            for (int j = 0; j < 4; j++) {
                float t = s[i][j] * c1;
                if (last) {
                    int rg = r0 + ty + 8*i;
                    int cg = jt*64 + tx + 16*j;
                    if (cg > rg) t = -1e30f;
                }
                s[i][j] = t;
            }

        // online softmax; row reductions across the 16 tx lanes (half-warp)
        #pragma unroll
        for (int i = 0; i < 4; i++) {
            float rm = fmaxf(fmaxf(s[i][0], s[i][1]), fmaxf(s[i][2], s[i][3]));
            #pragma unroll
            for (int off = 8; off >= 1; off >>= 1)
                rm = fmaxf(rm, __shfl_xor_sync(0xffffffffu, rm, off));
            float mn = fmaxf(m_r[i], rm);
            float alpha = exp2f(m_r[i] - mn);
            m_r[i] = mn;
            float rs = 0.f;
            #pragma unroll
            for (int j = 0; j < 4; j++) {
                float p = exp2f(s[i][j] - mn);
                s[i][j] = p;
                rs += p;
            }
            #pragma unroll
            for (int off = 8; off >= 1; off >>= 1)
                rs += __shfl_xor_sync(0xffffffffu, rs, off);
            l_r[i] = l_r[i]*alpha + rs;
            #pragma unroll
            for (int j = 0; j < 4; j++) o_r[i][j] *= alpha;
        }

        __syncthreads();   // all threads done reading KPs as K
        // write P^T into the K buffer: Pt[key][row], stride 33
        #pragma unroll
        for (int i = 0; i < 4; i++)
            #pragma unroll
            for (int j = 0; j < 4; j++)
                KPs[(tx + 16*j)*33 + ty + 8*i] = s[i][j];
        __syncthreads();

        // O += P V (outer-product over 64 keys; broadcast a, stride-1 b)
        #pragma unroll 4
        for (int c = 0; c < 64; c++) {
            float a[4], bb[4];
            #pragma unroll
            for (int i = 0; i < 4; i++) a[i] = KPs[c*33 + ty + 8*i];
            #pragma unroll
            for (int j = 0; j < 4; j++) bb[j] = Vs[c*64 + tx + 16*j];
            #pragma unroll
            for (int i = 0; i < 4; i++)
                #pragma unroll
                for (int j = 0; j < 4; j++)
                    o_r[i][j] = fmaf(a[i], bb[j], o_r[i][j]);
        }
    }

    // epilogue: normalize and store
    #pragma unroll
    for (int i = 0; i < 4; i++) {
        float inv = 1.f / l_r[i];
        #pragma unroll
        for (int j = 0; j < 4; j++)
            g_oh[base + (size_t)(r0 + ty + 8*i)*NHD + tx + 16*j] = o_r[i][j] * inv;
    }
}

// ---------------- launch ----------------------------------------------------
extern "C" void kernel_launch(void* const* d_in, const int* in_sizes, int n_in,
                              void* d_out, int out_size) {
    const float* query = (const float*)d_in[0];
    const float* key   = (const float*)d_in[1];
    const float* value = (const float*)d_in[2];
    // d_in[3] = mask (causal, reconstructed analytically — unused)
    const float* Wq   = (const float*)d_in[4];
    const float* Wk   = (const float*)d_in[5];
    const float* Wv   = (const float*)d_in[6];
    const float* wq_h = (const float*)d_in[7];
    const float* bq_h = (const float*)d_in[8];
    const float* wk_h = (const float*)d_in[9];
    const float* bk_h = (const float*)d_in[10];
    const float* wv_h = (const float*)d_in[11];
    const float* bv_h = (const float*)d_in[12];
    const float* Wo   = (const float*)d_in[13];
    float* out = (float*)d_out;

    zero_wcomb_kernel<<<(ND*NHD + 255)/256, 256>>>();
    wored_kernel<<<NHD, 256>>>(Wo);
    combine_kernel<<<dim3(8, 1, 24), 256>>>(Wq, Wk, Wv, wq_h, wk_h, wv_h);
    proj_kernel<<<dim3(NM/128, 1, 3), 256>>>(query, key, value, bq_h, bk_h, bv_h);
    attn_kernel<<<dim3(64, NB), 128>>>();
    outgemm_kernel<<<dim3(NM/128, ND/64), 256>>>(out);
}

// round 2
// speedup vs baseline: 1.3890x; 1.3890x over previous
#include <cuda_runtime.h>
#include <cuda_bf16.h>
#include <math.h>

// Problem constants
#define NB 4
#define NS 2048
#define ND 1024
#define NHD 64
#define NM (NB*NS)   // 8192

// ---------------- scratch (device globals; no allocation allowed) ----------
__device__ float g_Wqh[ND*NHD];     // Wq @ wq_h   [1024,64]
__device__ float g_Wkh[ND*NHD];
__device__ float g_Wvh[ND*NHD];
__device__ float g_Wored[NHD*ND];   // head-summed Wo [64,1024]
__device__ float g_qh[NM*NHD];      // per-head projections [8192,64]
__device__ float g_kh[NM*NHD];
__device__ float g_vh[NM*NHD];
__device__ float g_oh[NM*NHD];      // attention output [8192,64]

// ---------------- tiny kernels --------------------------------------------
__global__ void zero_wcomb_kernel() {
    int i = blockIdx.x*blockDim.x + threadIdx.x;
    if (i < ND*NHD) { g_Wqh[i]=0.f; g_Wkh[i]=0.f; g_Wvh[i]=0.f; }
}

// Wo_red[h,e] = sum_{j<16} Wo[(j*64+h), e]
__global__ void wored_kernel(const float* __restrict__ Wo) {
    int h = blockIdx.x;
    for (int e = threadIdx.x; e < ND; e += blockDim.x) {
        float s = 0.f;
        #pragma unroll
        for (int j = 0; j < 16; j++) s += Wo[(size_t)(j*NHD + h)*ND + e];
        g_Wored[h*ND + e] = s;
    }
}

// ---------------- bf16-split tensor-core GEMM core -------------------------
// C tile 128(m) x 64(n), BK=32, 256 threads = 8 warps in 4x2 grid,
// warp tile 32x32 = 2(m16) x 4(n8) mma fragments.
// fp32 operands are split x = hi + lo (bf16 each); product emulated with
// 3 MMAs (hh + hl + lh), error ~2^-16 per element.

__device__ __forceinline__ void bf16_split_pack(float x0, float x1,
                                                unsigned &hi, unsigned &lo) {
    __nv_bfloat16 h0 = __float2bfloat16_rn(x0);
    __nv_bfloat16 h1 = __float2bfloat16_rn(x1);
    __nv_bfloat16 l0 = __float2bfloat16_rn(x0 - __bfloat162float(h0));
    __nv_bfloat16 l1 = __float2bfloat16_rn(x1 - __bfloat162float(h1));
    hi = (unsigned)__bfloat16_as_ushort(h0) | ((unsigned)__bfloat16_as_ushort(h1) << 16);
    lo = (unsigned)__bfloat16_as_ushort(l0) | ((unsigned)__bfloat16_as_ushort(l1) << 16);
}

__device__ __forceinline__ void ldsm4(unsigned r[4], unsigned addr) {
    asm volatile("ldmatrix.sync.aligned.m8n8.x4.shared.b16 {%0,%1,%2,%3}, [%4];"
                 : "=r"(r[0]), "=r"(r[1]), "=r"(r[2]), "=r"(r[3]) : "r"(addr));
}
__device__ __forceinline__ void ldsm4t(unsigned r[4], unsigned addr) {
    asm volatile("ldmatrix.sync.aligned.m8n8.x4.trans.shared.b16 {%0,%1,%2,%3}, [%4];"
                 : "=r"(r[0]), "=r"(r[1]), "=r"(r[2]), "=r"(r[3]) : "r"(addr));
}
__device__ __forceinline__ void mma_bf16(float c[4], const unsigned a[4],
                                         unsigned b0, unsigned b1) {
    asm volatile(
        "mma.sync.aligned.m16n8k16.row.col.f32.bf16.bf16.f32 "
        "{%0,%1,%2,%3},{%4,%5,%6,%7},{%8,%9},{%0,%1,%2,%3};"
        : "+f"(c[0]), "+f"(c[1]), "+f"(c[2]), "+f"(c[3])
        : "r"(a[0]), "r"(a[1]), "r"(a[2]), "r"(a[3]), "r"(b0), "r"(b1));
}

// smem geometry (bytes):
//  A hi/lo: 128 rows x (32 bf16 = 64B + 16B pad = 80B)  -> ldmatrix rows hit
//           distinct bank groups (80*i mod 128 covers all 32 banks)
//  B hi/lo: 32 k-rows x (64 bf16 = 128B + 16B pad = 144B)
#define SM_A_HI 0
#define SM_A_LO 10240
#define SM_B_HI 20480
#define SM_B_LO 25088
#define SM_TOT  29696

template<bool ATOMIC, bool BIAS>
__device__ __forceinline__ void mma_gemm_core(
    const float* __restrict__ A, int lda,
    const float* __restrict__ Bm, int ldb,
    float* __restrict__ C, int ldc,
    const float* __restrict__ bias,
    int m0, int n0, int kStart, int kLen)
{
    __shared__ __align__(16) unsigned char sm[SM_TOT];
    unsigned sbase = (unsigned)__cvta_generic_to_shared(sm);
    int tid  = threadIdx.x;
    int lane = tid & 31, wid = tid >> 5;
    int wm = wid >> 1, wn = wid & 1;
    int lRow = lane & 15;            // ldmatrix row-within-group (A rows / B k-rows)
    int lHi  = (lane >> 4) << 3;     // second-coordinate offset for lanes 16-31

    float c[2][4][4];
    #pragma unroll
    for (int mt = 0; mt < 2; mt++)
        #pragma unroll
        for (int nt = 0; nt < 4; nt++)
            #pragma unroll
            for (int i = 0; i < 4; i++) c[mt][nt][i] = 0.f;

    for (int kb = 0; kb < kLen; kb += 32) {
        int k0 = kStart + kb;
        __syncthreads();
        // ---- produce A tile 128x32 (f32 -> split bf16 hi/lo) ----
        #pragma unroll
        for (int p = 0; p < 4; p++) {
            int idx = tid + p*256;
            int r = idx >> 3, c4 = idx & 7;
            float4 v = *(const float4*)(A + (size_t)(m0 + r)*lda + k0 + c4*4);
            unsigned h01, l01, h23, l23;
            bf16_split_pack(v.x, v.y, h01, l01);
            bf16_split_pack(v.z, v.w, h23, l23);
            *(uint2*)(sm + SM_A_HI + r*80 + c4*8) = make_uint2(h01, h23);
            *(uint2*)(sm + SM_A_LO + r*80 + c4*8) = make_uint2(l01, l23);
        }
        // ---- produce B tile 32x64, natural [k][n] layout ----
        #pragma unroll
        for (int p = 0; p < 2; p++) {
            int idx = tid + p*256;
            int r = idx >> 4, c4 = idx & 15;
            float4 v = *(const float4*)(Bm + (size_t)(k0 + r)*ldb + n0 + c4*4);
            unsigned h01, l01, h23, l23;
            bf16_split_pack(v.x, v.y, h01, l01);
            bf16_split_pack(v.z, v.w, h23, l23);
            *(uint2*)(sm + SM_B_HI + r*144 + c4*8) = make_uint2(h01, h23);
            *(uint2*)(sm + SM_B_LO + r*144 + c4*8) = make_uint2(l01, l23);
        }
        __syncthreads();
        // ---- compute: two k16 slices ----
        #pragma unroll
        for (int ks = 0; ks < 32; ks += 16) {
            unsigned ah[2][4], al[2][4], bh[2][4], bl[2][4];
            #pragma unroll
            for (int mt = 0; mt < 2; mt++) {
                unsigned off = sbase + SM_A_HI
                             + (unsigned)((wm*32 + mt*16 + lRow)*80 + (ks + lHi)*2);
                ldsm4(ah[mt], off);
                ldsm4(al[mt], off + (SM_A_LO - SM_A_HI));
            }
            #pragma unroll
            for (int np = 0; np < 2; np++) {
                unsigned off = sbase + SM_B_HI
                             + (unsigned)((ks + lRow)*144 + (wn*32 + np*16 + lHi)*2);
                ldsm4t(bh[np], off);
                ldsm4t(bl[np], off + (SM_B_LO - SM_B_HI));
            }
            #pragma unroll
            for (int mt = 0; mt < 2; mt++)
                #pragma unroll
                for (int nt = 0; nt < 4; nt++) {
                    unsigned b0h = bh[nt >> 1][(nt & 1)*2], b1h = bh[nt >> 1][(nt & 1)*2 + 1];
                    unsigned b0l = bl[nt >> 1][(nt & 1)*2], b1l = bl[nt >> 1][(nt & 1)*2 + 1];
                    mma_bf16(c[mt][nt], ah[mt], b0h, b1h);   // hi*hi
                    mma_bf16(c[mt][nt], ah[mt], b0l, b1l);   // hi*lo
                    mma_bf16(c[mt][nt], al[mt], b0h, b1h);   // lo*hi
                }
        }
    }
    // ---- epilogue ----
    #pragma unroll
    for (int mt = 0; mt < 2; mt++)
        #pragma unroll
        for (int nt = 0; nt < 4; nt++) {
            int row = m0 + wm*32 + mt*16 + (lane >> 2);
            int col = n0 + wn*32 + nt*8 + (lane & 3)*2;
            float v0 = c[mt][nt][0], v1 = c[mt][nt][1];
            float v2 = c[mt][nt][2], v3 = c[mt][nt][3];
            if (BIAS) {
                v0 += bias[col - n0];     v1 += bias[col + 1 - n0];
                v2 += bias[col - n0];     v3 += bias[col + 1 - n0];
            }
            if (ATOMIC) {
                atomicAdd(&C[(size_t)row*ldc + col],       v0);
                atomicAdd(&C[(size_t)row*ldc + col + 1],   v1);
                atomicAdd(&C[(size_t)(row+8)*ldc + col],   v2);
                atomicAdd(&C[(size_t)(row+8)*ldc + col+1], v3);
            } else {
                *(float2*)(C + (size_t)row*ldc + col)     = make_float2(v0, v1);
                *(float2*)(C + (size_t)(row+8)*ldc + col) = make_float2(v2, v3);
            }
        }
}

// Combined weights: Wxh = Wx @ wx_h, split-K(8 x 128) with atomic accumulate.
__global__ void combine_kernel(
    const float* __restrict__ Wq, const float* __restrict__ Wk, const float* __restrict__ Wv,
    const float* __restrict__ wqh, const float* __restrict__ wkh, const float* __restrict__ wvh)
{
    int z = blockIdx.z;
    int which = z >> 3;
    int chunk = z & 7;
    const float* A  = (which==0) ? Wq  : (which==1) ? Wk  : Wv;
    const float* Bm = (which==0) ? wqh : (which==1) ? wkh : wvh;
    float*       C  = (which==0) ? g_Wqh : (which==1) ? g_Wkh : g_Wvh;
    mma_gemm_core<true,false>(A, ND, Bm, NHD, C, NHD, nullptr,
                              blockIdx.x*128, 0, chunk*128, 128);
}

// Per-head projections: xh = X @ Wxh + b.  grid (64, 1, 3)
__global__ void proj_kernel(
    const float* __restrict__ q, const float* __restrict__ k, const float* __restrict__ v,
    const float* __restrict__ bq, const float* __restrict__ bk, const float* __restrict__ bv)
{
    int which = blockIdx.z;
    const float* A    = (which==0) ? q     : (which==1) ? k     : v;
    const float* W    = (which==0) ? g_Wqh : (which==1) ? g_Wkh : g_Wvh;
    const float* bias = (which==0) ? bq    : (which==1) ? bk    : bv;
    float*       C    = (which==0) ? g_qh  : (which==1) ? g_kh  : g_vh;
    mma_gemm_core<false,true>(A, ND, W, NHD, C, NHD, bias, blockIdx.x*128, 0, 0, ND);
}

// Final: out = oh @ Wo_red.  grid (64, 16)
__global__ void outgemm_kernel(float* __restrict__ out) {
    mma_gemm_core<false,false>(g_oh, NHD, g_Wored, ND, out, ND, nullptr,
                               blockIdx.x*128, blockIdx.y*64, 0, NHD);
}

// ---------------- causal flash attention, single head, HD=64 ---------------
// (unchanged from round 1 — tensor-core port is next round)
__global__ void attn_kernel() {
    __shared__ float Qs[32*68];
    __shared__ float KPs[64*68];
    __shared__ float Vs[64*64];

    int tid = threadIdx.x;
    int tx = tid & 15, ty = tid >> 4;
    int qb = 63 - (int)blockIdx.x;
    int b  = blockIdx.y;
    size_t base = (size_t)b * NS * NHD;
    int r0 = qb * 32;

    #pragma unroll
    for (int p = 0; p < 4; p++) {
        int idx = tid + p*128;
        int r = idx >> 4, hc = idx & 15;
        float4 v = *(const float4*)(&g_qh[base + (size_t)(r0 + r)*NHD + hc*4]);
        *(float4*)(&Qs[r*68 + hc*4]) = v;
    }

    float m_r[4], l_r[4], o_r[4][4];
    #pragma unroll
    for (int i = 0; i < 4; i++) {
        m_r[i] = -1e30f; l_r[i] = 0.f;
        #pragma unroll
        for (int j = 0; j < 4; j++) o_r[i][j] = 0.f;
    }
    const float c1 = 0.125f * 1.4426950408889634f;
    int nkt = (qb >> 1) + 1;

    for (int jt = 0; jt < nkt; jt++) {
        __syncthreads();
        #pragma unroll
        for (int p = 0; p < 8; p++) {
            int idx = tid + p*128;
            int r = idx >> 4, hc = idx & 15;
            size_t g = base + (size_t)(jt*64 + r)*NHD + hc*4;
            float4 kv = *(const float4*)(&g_kh[g]);
            *(float4*)(&KPs[r*68 + hc*4]) = kv;
            float4 vv = *(const float4*)(&g_vh[g]);
            *(float4*)(&Vs[r*64 + hc*4]) = vv;
        }
        __syncthreads();

        float s[4][4];
        #pragma unroll
        for (int i = 0; i < 4; i++)
            #pragma unroll
            for (int j = 0; j < 4; j++) s[i][j] = 0.f;
        #pragma unroll
        for (int hc = 0; hc < 16; hc++) {
            float4 a[4], bb[4];
            #pragma unroll
            for (int i = 0; i < 4; i++)
                a[i] = *(const float4*)(&Qs[(ty + 8*i)*68 + hc*4]);
            #pragma unroll
            for (int j = 0; j < 4; j++)
                bb[j] = *(const float4*)(&KPs[(tx + 16*j)*68 + hc*4]);
            #pragma unroll
            for (int i = 0; i < 4; i++)
                #pragma unroll
                for (int j = 0; j < 4; j++) {
                    s[i][j] = fmaf(a[i].x, bb[j].x, s[i][j]);
                    s[i][j] = fmaf(a[i].y, bb[j].y, s[i][j]);
                    s[i][j] = fmaf(a[i].z, bb[j].z, s[i][j]);
                    s[i][j] = fmaf(a[i].w, bb[j].w, s[i][j]);
                }
        }

        bool last = (jt == nkt - 1);
        #pragma unroll
        for (int i = 0; i < 4; i++)
            #pragma unroll
            for (int j = 0; j < 4; j++) {
                float t = s[i][j] * c1;
                if (last) {
                    int rg = r0 + ty + 8*i;
                    int cg = jt*64 + tx + 16*j;
                    if (cg > rg) t = -1e30f;
                }
                s[i][j] = t;
            }

        #pragma unroll
        for (int i = 0; i < 4; i++) {
            float rm = fmaxf(fmaxf(s[i][0], s[i][1]), fmaxf(s[i][2], s[i][3]));
            #pragma unroll
            for (int off = 8; off >= 1; off >>= 1)
                rm = fmaxf(rm, __shfl_xor_sync(0xffffffffu, rm, off));
            float mn = fmaxf(m_r[i], rm);
            float alpha = exp2f(m_r[i] - mn);
            m_r[i] = mn;
            float rs = 0.f;
            #pragma unroll
            for (int j = 0; j < 4; j++) {
                float p = exp2f(s[i][j] - mn);
                s[i][j] = p;
                rs += p;
            }
            #pragma unroll
            for (int off = 8; off >= 1; off >>= 1)
                rs += __shfl_xor_sync(0xffffffffu, rs, off);
            l_r[i] = l_r[i]*alpha + rs;
            #pragma unroll
            for (int j = 0; j < 4; j++) o_r[i][j] *= alpha;
        }

        __syncthreads();
        #pragma unroll
        for (int i = 0; i < 4; i++)
            #pragma unroll
            for (int j = 0; j < 4; j++)
                KPs[(tx + 16*j)*33 + ty + 8*i] = s[i][j];
        __syncthreads();

        #pragma unroll 4
        for (int cc = 0; cc < 64; cc++) {
            float a[4], bb[4];
            #pragma unroll
            for (int i = 0; i < 4; i++) a[i] = KPs[cc*33 + ty + 8*i];
            #pragma unroll
            for (int j = 0; j < 4; j++) bb[j] = Vs[cc*64 + tx + 16*j];
            #pragma unroll
            for (int i = 0; i < 4; i++)
                #pragma unroll
                for (int j = 0; j < 4; j++)
                    o_r[i][j] = fmaf(a[i], bb[j], o_r[i][j]);
        }
    }

    #pragma unroll
    for (int i = 0; i < 4; i++) {
        float inv = 1.f / l_r[i];
        #pragma unroll
        for (int j = 0; j < 4; j++)
            g_oh[base + (size_t)(r0 + ty + 8*i)*NHD + tx + 16*j] = o_r[i][j] * inv;
    }
}

// ---------------- launch ----------------------------------------------------
extern "C" void kernel_launch(void* const* d_in, const int* in_sizes, int n_in,
                              void* d_out, int out_size) {
    const float* query = (const float*)d_in[0];
    const float* key   = (const float*)d_in[1];
    const float* value = (const float*)d_in[2];
    // d_in[3] = mask (causal, reconstructed analytically — unused)
    const float* Wq   = (const float*)d_in[4];
    const float* Wk   = (const float*)d_in[5];
    const float* Wv   = (const float*)d_in[6];
    const float* wq_h = (const float*)d_in[7];
    const float* bq_h = (const float*)d_in[8];
    const float* wk_h = (const float*)d_in[9];
    const float* bk_h = (const float*)d_in[10];
    const float* wv_h = (const float*)d_in[11];
    const float* bv_h = (const float*)d_in[12];
    const float* Wo   = (const float*)d_in[13];
    float* out = (float*)d_out;

    zero_wcomb_kernel<<<(ND*NHD + 255)/256, 256>>>();
    wored_kernel<<<NHD, 256>>>(Wo);
    combine_kernel<<<dim3(8, 1, 24), 256>>>(Wq, Wk, Wv, wq_h, wk_h, wv_h);
    proj_kernel<<<dim3(NM/128, 1, 3), 256>>>(query, key, value, bq_h, bk_h, bv_h);
    attn_kernel<<<dim3(64, NB), 128>>>();
    outgemm_kernel<<<dim3(NM/128, ND/64), 256>>>(out);
}

// round 3
// speedup vs baseline: 2.4392x; 1.7561x over previous
#include <cuda_runtime.h>
#include <cuda_bf16.h>
#include <math.h>

// Problem constants
#define NB 4
#define NS 2048
#define ND 1024
#define NHD 64
#define NM (NB*NS)   // 8192

// ---------------- scratch (device globals; no allocation allowed) ----------
__device__ float g_Wqh[ND*NHD];
__device__ float g_Wkh[ND*NHD];
__device__ float g_Wvh[ND*NHD];
__device__ float g_Wored[NHD*ND];
__device__ float g_oh[NM*NHD];
__device__ __nv_bfloat16 g_qh_hi[NM*NHD], g_qh_lo[NM*NHD];
__device__ __nv_bfloat16 g_kh_hi[NM*NHD], g_kh_lo[NM*NHD];
__device__ __nv_bfloat16 g_vh_hi[NM*NHD], g_vh_lo[NM*NHD];

// ---------------- helpers ---------------------------------------------------
__device__ __forceinline__ void bf16_split_pack(float x0, float x1,
                                                unsigned &hi, unsigned &lo) {
    __nv_bfloat16 h0 = __float2bfloat16_rn(x0);
    __nv_bfloat16 h1 = __float2bfloat16_rn(x1);
    __nv_bfloat16 l0 = __float2bfloat16_rn(x0 - __bfloat162float(h0));
    __nv_bfloat16 l1 = __float2bfloat16_rn(x1 - __bfloat162float(h1));
    hi = (unsigned)__bfloat16_as_ushort(h0) | ((unsigned)__bfloat16_as_ushort(h1) << 16);
    lo = (unsigned)__bfloat16_as_ushort(l0) | ((unsigned)__bfloat16_as_ushort(l1) << 16);
}
__device__ __forceinline__ void ldsm4(unsigned r[4], unsigned addr) {
    asm volatile("ldmatrix.sync.aligned.m8n8.x4.shared.b16 {%0,%1,%2,%3}, [%4];"
                 : "=r"(r[0]), "=r"(r[1]), "=r"(r[2]), "=r"(r[3]) : "r"(addr));
}
__device__ __forceinline__ void ldsm4t(unsigned r[4], unsigned addr) {
    asm volatile("ldmatrix.sync.aligned.m8n8.x4.trans.shared.b16 {%0,%1,%2,%3}, [%4];"
                 : "=r"(r[0]), "=r"(r[1]), "=r"(r[2]), "=r"(r[3]) : "r"(addr));
}
__device__ __forceinline__ void mma_bf16(float c[4], const unsigned a[4],
                                         unsigned b0, unsigned b1) {
    asm volatile(
        "mma.sync.aligned.m16n8k16.row.col.f32.bf16.bf16.f32 "
        "{%0,%1,%2,%3},{%4,%5,%6,%7},{%8,%9},{%0,%1,%2,%3};"
        : "+f"(c[0]), "+f"(c[1]), "+f"(c[2]), "+f"(c[3])
        : "r"(a[0]), "r"(a[1]), "r"(a[2]), "r"(a[3]), "r"(b0), "r"(b1));
}
__device__ __forceinline__ void cpa16(unsigned dst, const void* src) {
    asm volatile("cp.async.cg.shared.global [%0], [%1], 16;" :: "r"(dst), "l"(src));
}
#define CP_COMMIT asm volatile("cp.async.commit_group;")
#define CP_WAIT1  asm volatile("cp.async.wait_group 1;")

// ---------------- tiny kernels ----------------------------------------------
__global__ void zero_wcomb_kernel() {
    int i = blockIdx.x*blockDim.x + threadIdx.x;
    if (i < ND*NHD) { g_Wqh[i]=0.f; g_Wkh[i]=0.f; g_Wvh[i]=0.f; }
}
__global__ void wored_kernel(const float* __restrict__ Wo) {
    int h = blockIdx.x;
    for (int e = threadIdx.x; e < ND; e += blockDim.x) {
        float s = 0.f;
        #pragma unroll
        for (int j = 0; j < 16; j++) s += Wo[(size_t)(j*NHD + h)*ND + e];
        g_Wored[h*ND + e] = s;
    }
}

// ---------------- M64xN64 bf16-split tensor-core GEMM core ------------------
// 256 thr = 8 warps (wm 0..3 x wn 0..1), warp = 16m x 32n, BK=32,
// register-staged gmem prefetch overlaps LDG with mma.
#define G_SM_A_HI 0
#define G_SM_A_LO 5120
#define G_SM_B_HI 10240
#define G_SM_B_LO 14848
#define G_SM_TOT  19456

// MODE: 0 = f32 store, 1 = f32 atomicAdd, 2 = bias + bf16 hi/lo pair store
template<int MODE>
__device__ __forceinline__ void mma_gemm_core64(
    const float* __restrict__ A, int lda,
    const float* __restrict__ Bm, int ldb,
    float* __restrict__ C, int ldc,
    __nv_bfloat16* __restrict__ Chi, __nv_bfloat16* __restrict__ Clo,
    const float* __restrict__ bias,
    int m0, int n0, int kStart, int kLen)
{
    __shared__ __align__(16) unsigned char sm[G_SM_TOT];
    unsigned sbase = (unsigned)__cvta_generic_to_shared(sm);
    int tid = threadIdx.x, lane = tid & 31, wid = tid >> 5;
    int wm = wid >> 1, wn = wid & 1;
    int lRow = lane & 15, lHi = (lane >> 4) << 3;

    float c[4][4] = {};
    float4 aReg[2], bReg[2];
    #pragma unroll
    for (int p = 0; p < 2; p++) {
        int idx = tid + p*256;
        aReg[p] = *(const float4*)(A + (size_t)(m0 + (idx>>3))*lda + kStart + (idx&7)*4);
        bReg[p] = *(const float4*)(Bm + (size_t)(kStart + (idx>>4))*ldb + n0 + (idx&15)*4);
    }
    for (int kb = 0; kb < kLen; kb += 32) {
        #pragma unroll
        for (int p = 0; p < 2; p++) {
            int idx = tid + p*256;
            {   int r = idx>>3, c4 = idx&7;
                unsigned h01,l01,h23,l23;
                bf16_split_pack(aReg[p].x, aReg[p].y, h01, l01);
                bf16_split_pack(aReg[p].z, aReg[p].w, h23, l23);
                *(uint2*)(sm + G_SM_A_HI + r*80 + c4*8) = make_uint2(h01,h23);
                *(uint2*)(sm + G_SM_A_LO + r*80 + c4*8) = make_uint2(l01,l23);
            }
            {   int r = idx>>4, c4 = idx&15;
                unsigned h01,l01,h23,l23;
                bf16_split_pack(bReg[p].x, bReg[p].y, h01, l01);
                bf16_split_pack(bReg[p].z, bReg[p].w, h23, l23);
                *(uint2*)(sm + G_SM_B_HI + r*144 + c4*8) = make_uint2(h01,h23);
                *(uint2*)(sm + G_SM_B_LO + r*144 + c4*8) = make_uint2(l01,l23);
            }
        }
        __syncthreads();
        if (kb + 32 < kLen) {      // prefetch next slice; LDGs overlap mma below
            int k0 = kStart + kb + 32;
            #pragma unroll
            for (int p = 0; p < 2; p++) {
                int idx = tid + p*256;
                aReg[p] = *(const float4*)(A + (size_t)(m0 + (idx>>3))*lda + k0 + (idx&7)*4);
                bReg[p] = *(const float4*)(Bm + (size_t)(k0 + (idx>>4))*ldb + n0 + (idx&15)*4);
            }
        }
        #pragma unroll
        for (int ks = 0; ks < 32; ks += 16) {
            unsigned ah[4], al[4], bh[2][4], bl[2][4];
            unsigned offA = sbase + G_SM_A_HI + (unsigned)((wm*16 + lRow)*80 + (ks + lHi)*2);
            ldsm4(ah, offA);
            ldsm4(al, offA + (G_SM_A_LO - G_SM_A_HI));
            #pragma unroll
            for (int np = 0; np < 2; np++) {
                unsigned offB = sbase + G_SM_B_HI + (unsigned)((ks + lRow)*144 + (wn*32 + np*16 + lHi)*2);
                ldsm4t(bh[np], offB);
                ldsm4t(bl[np], offB + (G_SM_B_LO - G_SM_B_HI));
            }
            #pragma unroll
            for (int nt = 0; nt < 4; nt++) {
                unsigned b0h = bh[nt>>1][(nt&1)*2], b1h = bh[nt>>1][(nt&1)*2+1];
                unsigned b0l = bl[nt>>1][(nt&1)*2], b1l = bl[nt>>1][(nt&1)*2+1];
                mma_bf16(c[nt], ah, b0h, b1h);
                mma_bf16(c[nt], ah, b0l, b1l);
                mma_bf16(c[nt], al, b0h, b1h);
            }
        }
        __syncthreads();
    }
    int rowL = m0 + wm*16 + (lane>>2);
    #pragma unroll
    for (int nt = 0; nt < 4; nt++) {
        int col = n0 + wn*32 + nt*8 + (lane&3)*2;
        float v0 = c[nt][0], v1 = c[nt][1], v2 = c[nt][2], v3 = c[nt][3];
        if (MODE == 2) {
            v0 += bias[col-n0]; v1 += bias[col+1-n0];
            v2 += bias[col-n0]; v3 += bias[col+1-n0];
        }
        if (MODE == 0) {
            *(float2*)(C + (size_t)rowL*ldc + col)     = make_float2(v0,v1);
            *(float2*)(C + (size_t)(rowL+8)*ldc + col) = make_float2(v2,v3);
        } else if (MODE == 1) {
            atomicAdd(&C[(size_t)rowL*ldc+col],       v0);
            atomicAdd(&C[(size_t)rowL*ldc+col+1],     v1);
            atomicAdd(&C[(size_t)(rowL+8)*ldc+col],   v2);
            atomicAdd(&C[(size_t)(rowL+8)*ldc+col+1], v3);
        } else {
            unsigned h01,l01,h23,l23;
            bf16_split_pack(v0,v1,h01,l01);
            bf16_split_pack(v2,v3,h23,l23);
            *(unsigned*)(Chi + (size_t)rowL*NHD + col)     = h01;
            *(unsigned*)(Clo + (size_t)rowL*NHD + col)     = l01;
            *(unsigned*)(Chi + (size_t)(rowL+8)*NHD + col) = h23;
            *(unsigned*)(Clo + (size_t)(rowL+8)*NHD + col) = l23;
        }
    }
}

// Wxh = Wx @ wx_h, split-K(8x128), atomic. grid (16, 1, 24)
__global__ void combine_kernel(
    const float* __restrict__ Wq, const float* __restrict__ Wk, const float* __restrict__ Wv,
    const float* __restrict__ wqh, const float* __restrict__ wkh, const float* __restrict__ wvh)
{
    int z = blockIdx.z;
    int which = z >> 3, chunk = z & 7;
    const float* A  = (which==0) ? Wq  : (which==1) ? Wk  : Wv;
    const float* Bm = (which==0) ? wqh : (which==1) ? wkh : wvh;
    float*       C  = (which==0) ? g_Wqh : (which==1) ? g_Wkh : g_Wvh;
    mma_gemm_core64<1>(A, ND, Bm, NHD, C, NHD, nullptr, nullptr, nullptr,
                       blockIdx.x*64, 0, chunk*128, 128);
}

// xh = X @ Wxh + b, output split bf16 hi/lo. grid (128, 1, 3)
__global__ void proj_kernel(
    const float* __restrict__ q, const float* __restrict__ k, const float* __restrict__ v,
    const float* __restrict__ bq, const float* __restrict__ bk, const float* __restrict__ bv)
{
    int which = blockIdx.z;
    const float* A    = (which==0) ? q     : (which==1) ? k     : v;
    const float* W    = (which==0) ? g_Wqh : (which==1) ? g_Wkh : g_Wvh;
    const float* bias = (which==0) ? bq    : (which==1) ? bk    : bv;
    __nv_bfloat16* Chi = (which==0) ? g_qh_hi : (which==1) ? g_kh_hi : g_vh_hi;
    __nv_bfloat16* Clo = (which==0) ? g_qh_lo : (which==1) ? g_kh_lo : g_vh_lo;
    mma_gemm_core64<2>(A, ND, W, NHD, nullptr, 0, Chi, Clo, bias,
                       blockIdx.x*64, 0, 0, ND);
}

// out = oh @ Wo_red. grid (128, 16)
__global__ void outgemm_kernel(float* __restrict__ out) {
    mma_gemm_core64<0>(g_oh, NHD, g_Wored, ND, out, ND, nullptr, nullptr, nullptr,
                       blockIdx.x*64, blockIdx.y*64, 0, NHD);
}

// ---------------- tensor-core causal flash attention ------------------------
// BM=64, BN=32, 128 thr = 4 warps each owning 16 rows. Split-bf16 3-MMA for
// QK^T and PV. K/V bf16 hi/lo streamed via cp.async, 2-stage double buffer.
// smem: Q hi/lo 16K + 2 stages x (Khi,Klo,Vhi,Vlo 4K each) = 48K exactly.
#define AQ_HI 0
#define AQ_LO 8192
#define AST   16384
#define ASTSZ 16384

__device__ __forceinline__ void attn_load_stage(unsigned sbst, size_t kvbase, int tid) {
    #pragma unroll
    for (int p = 0; p < 2; p++) {
        int idx = tid + p*128;           // 0..255 -> 32 rows x 8 chunks
        int r = idx >> 3, c = idx & 7;
        unsigned sw = (unsigned)(r*128 + ((c ^ (r & 7)) << 4));
        size_t g = kvbase + (size_t)r*NHD + c*8;
        cpa16(sbst + 0     + sw, g_kh_hi + g);
        cpa16(sbst + 4096  + sw, g_kh_lo + g);
        cpa16(sbst + 8192  + sw, g_vh_hi + g);
        cpa16(sbst + 12288 + sw, g_vh_lo + g);
    }
}

__global__ void __launch_bounds__(128) attn_kernel() {
    __shared__ __align__(16) unsigned char sm[49152];
    unsigned sb = (unsigned)__cvta_generic_to_shared(sm);
    int tid = threadIdx.x, lane = tid & 31, wid = tid >> 5;
    int qb = blockIdx.x, b = blockIdx.y;
    size_t base = (size_t)b * NS * NHD;
    int r0 = qb * 64;
    int nkt = 2*qb + 2;

    // Q tile (64x64 hi/lo) via cp.async, swizzled
    #pragma unroll
    for (int p = 0; p < 4; p++) {
        int idx = tid + p*128;           // 0..511 -> 64 rows x 8 chunks
        int r = idx >> 3, c = idx & 7;
        unsigned sw = (unsigned)(r*128 + ((c ^ (r & 7)) << 4));
        size_t g = base + (size_t)(r0 + r)*NHD + c*8;
        cpa16(sb + AQ_HI + sw, g_qh_hi + g);
        cpa16(sb + AQ_LO + sw, g_qh_lo + g);
    }
    CP_COMMIT;
    attn_load_stage(sb + AST, base, tid);    // stage 0 = keys [0,32)
    CP_COMMIT;
    CP_WAIT1;                                 // Q group done
    __syncthreads();

    // hoist Q fragments to registers (invariant over kv loop)
    unsigned qh_f[4][4], ql_f[4][4];
    {
        int row = wid*16 + (lane & 15);
        #pragma unroll
        for (int c = 0; c < 4; c++) {
            int ch = 2*c + (lane >> 4);
            unsigned addr = sb + AQ_HI + (unsigned)(row*128 + ((ch ^ (row & 7)) << 4));
            ldsm4(qh_f[c], addr);
            ldsm4(ql_f[c], addr + (AQ_LO - AQ_HI));
        }
    }

    float o[8][4] = {};
    float m0r = -1e30f, m1r = -1e30f, l0r = 0.f, l1r = 0.f;
    const float c1 = 0.125f * 1.4426950408889634f;   // 1/sqrt(64) * log2(e)

    for (int jt = 0; jt < nkt; jt++) {
        unsigned cur = sb + AST + (unsigned)((jt & 1) * ASTSZ);
        if (jt + 1 < nkt)
            attn_load_stage(sb + AST + (unsigned)(((jt+1) & 1) * ASTSZ),
                            base + (size_t)(jt+1)*32*NHD, tid);
        CP_COMMIT;
        CP_WAIT1;                // stage jt complete (newest group may be in flight)
        __syncthreads();

        // ---- S = Q K^T (3-MMA split) ----
        float s[4][4] = {};
        #pragma unroll
        for (int c = 0; c < 4; c++) {
            int ch = 2*c + ((lane >> 3) & 1);
            int keyr = ((lane >> 4) << 3) + (lane & 7);
            unsigned a0 = cur + (unsigned)(keyr*128 + ((ch ^ (keyr & 7)) << 4));
            unsigned a1 = a0 + 16*128;
            unsigned kh0[4], kh1[4], kl0[4], kl1[4];
            ldsm4(kh0, a0); ldsm4(kh1, a1);
            ldsm4(kl0, a0 + 4096); ldsm4(kl1, a1 + 4096);
            mma_bf16(s[0], qh_f[c], kh0[0], kh0[1]);
            mma_bf16(s[0], qh_f[c], kl0[0], kl0[1]);
            mma_bf16(s[0], ql_f[c], kh0[0], kh0[1]);
            mma_bf16(s[1], qh_f[c], kh0[2], kh0[3]);
            mma_bf16(s[1], qh_f[c], kl0[2], kl0[3]);
            mma_bf16(s[1], ql_f[c], kh0[2], kh0[3]);
            mma_bf16(s[2], qh_f[c], kh1[0], kh1[1]);
            mma_bf16(s[2], qh_f[c], kl1[0], kl1[1]);
            mma_bf16(s[2], ql_f[c], kh1[0], kh1[1]);
            mma_bf16(s[3], qh_f[c], kh1[2], kh1[3]);
            mma_bf16(s[3], qh_f[c], kl1[2], kl1[3]);
            mma_bf16(s[3], ql_f[c], kh1[2], kh1[3]);
        }

        // ---- scale + causal mask (diagonal iters only) ----
        bool dom = (jt >= 2*qb);
        int rgl = r0 + wid*16 + (lane >> 2);
        #pragma unroll
        for (int f = 0; f < 4; f++) {
            int kg = jt*32 + f*8 + (lane & 3)*2;
            #pragma unroll
            for (int e = 0; e < 4; e++) {
                float t = s[f][e] * c1;
                if (dom && (kg + (e & 1)) > (rgl + ((e >= 2) ? 8 : 0))) t = -1e30f;
                s[f][e] = t;
            }
        }

        // ---- online softmax (rows fully in-warp: reduce over lane&3) ----
        float mx0 = -1e30f, mx1 = -1e30f;
        #pragma unroll
        for (int f = 0; f < 4; f++) {
            mx0 = fmaxf(mx0, fmaxf(s[f][0], s[f][1]));
            mx1 = fmaxf(mx1, fmaxf(s[f][2], s[f][3]));
        }
        mx0 = fmaxf(mx0, __shfl_xor_sync(0xffffffffu, mx0, 1));
        mx0 = fmaxf(mx0, __shfl_xor_sync(0xffffffffu, mx0, 2));
        mx1 = fmaxf(mx1, __shfl_xor_sync(0xffffffffu, mx1, 1));
        mx1 = fmaxf(mx1, __shfl_xor_sync(0xffffffffu, mx1, 2));
        float mn0 = fmaxf(m0r, mx0), mn1 = fmaxf(m1r, mx1);
        float al0 = exp2f(m0r - mn0), al1 = exp2f(m1r - mn1);
        m0r = mn0; m1r = mn1;
        float rs0 = 0.f, rs1 = 0.f;
        #pragma unroll
        for (int f = 0; f < 4; f++) {
            s[f][0] = exp2f(s[f][0] - mn0);
            s[f][1] = exp2f(s[f][1] - mn0);
            s[f][2] = exp2f(s[f][2] - mn1);
            s[f][3] = exp2f(s[f][3] - mn1);
            rs0 += s[f][0] + s[f][1];
            rs1 += s[f][2] + s[f][3];
        }
        rs0 += __shfl_xor_sync(0xffffffffu, rs0, 1);
        rs0 += __shfl_xor_sync(0xffffffffu, rs0, 2);
        rs1 += __shfl_xor_sync(0xffffffffu, rs1, 1);
        rs1 += __shfl_xor_sync(0xffffffffu, rs1, 2);
        l0r = l0r*al0 + rs0;
        l1r = l1r*al1 + rs1;
        #pragma unroll
        for (int f = 0; f < 8; f++) {
            o[f][0] *= al0; o[f][1] *= al0;
            o[f][2] *= al1; o[f][3] *= al1;
        }

        // ---- O += P V (3-MMA split; P packed from registers) ----
        #pragma unroll
        for (int ka = 0; ka < 2; ka++) {
            unsigned ph[4], pl[4];
            bf16_split_pack(s[2*ka][0],   s[2*ka][1],   ph[0], pl[0]);
            bf16_split_pack(s[2*ka][2],   s[2*ka][3],   ph[1], pl[1]);
            bf16_split_pack(s[2*ka+1][0], s[2*ka+1][1], ph[2], pl[2]);
            bf16_split_pack(s[2*ka+1][2], s[2*ka+1][3], ph[3], pl[3]);
            #pragma unroll
            for (int fp = 0; fp < 4; fp++) {
                int ch = 2*fp + (lane >> 4);
                int kvr = ka*16 + (lane & 15);
                unsigned av = cur + 8192 + (unsigned)(kvr*128 + ((ch ^ (kvr & 7)) << 4));
                unsigned vh[4], vl[4];
                ldsm4t(vh, av); ldsm4t(vl, av + 4096);
                mma_bf16(o[2*fp],   ph, vh[0], vh[1]);
                mma_bf16(o[2*fp],   pl, vh[0], vh[1]);
                mma_bf16(o[2*fp],   ph, vl[0], vl[1]);
                mma_bf16(o[2*fp+1], ph, vh[2], vh[3]);
                mma_bf16(o[2*fp+1], pl, vh[2], vh[3]);
                mma_bf16(o[2*fp+1], ph, vl[2], vl[3]);
            }
        }
        __syncthreads();   // all warps done with cur before it is overwritten
    }

    // ---- epilogue ----
    float inv0 = 1.f / l0r, inv1 = 1.f / l1r;
    int rowg = r0 + wid*16 + (lane >> 2);
    #pragma unroll
    for (int f = 0; f < 8; f++) {
        int hd = f*8 + (lane & 3)*2;
        *(float2*)(g_oh + base + (size_t)rowg*NHD + hd) =
            make_float2(o[f][0]*inv0, o[f][1]*inv0);
        *(float2*)(g_oh + base + (size_t)(rowg+8)*NHD + hd) =
            make_float2(o[f][2]*inv1, o[f][3]*inv1);
    }
}

// ---------------- launch ----------------------------------------------------
extern "C" void kernel_launch(void* const* d_in, const int* in_sizes, int n_in,
                              void* d_out, int out_size) {
    const float* query = (const float*)d_in[0];
    const float* key   = (const float*)d_in[1];
    const float* value = (const float*)d_in[2];
    // d_in[3] = mask (causal, reconstructed analytically — unused)
    const float* Wq   = (const float*)d_in[4];
    const float* Wk   = (const float*)d_in[5];
    const float* Wv   = (const float*)d_in[6];
    const float* wq_h = (const float*)d_in[7];
    const float* bq_h = (const float*)d_in[8];
    const float* wk_h = (const float*)d_in[9];
    const float* bk_h = (const float*)d_in[10];
    const float* wv_h = (const float*)d_in[11];
    const float* bv_h = (const float*)d_in[12];
    const float* Wo   = (const float*)d_in[13];
    float* out = (float*)d_out;

    zero_wcomb_kernel<<<(ND*NHD + 255)/256, 256>>>();
    wored_kernel<<<NHD, 256>>>(Wo);
    combine_kernel<<<dim3(16, 1, 24), 256>>>(Wq, Wk, Wv, wq_h, wk_h, wv_h);
    proj_kernel<<<dim3(128, 1, 3), 256>>>(query, key, value, bq_h, bk_h, bv_h);
    attn_kernel<<<dim3(32, NB), 128>>>();
    outgemm_kernel<<<dim3(128, 16), 256>>>(out);
}

// round 4
// speedup vs baseline: 2.9360x; 1.2037x over previous
#include <cuda_runtime.h>
#include <cuda_bf16.h>
#include <math.h>

// Problem constants
#define NB 4
#define NS 2048
#define ND 1024
#define NHD 64
#define NM (NB*NS)   // 8192

// ---------------- scratch (device globals; no allocation allowed) ----------
__device__ float g_Wqh[ND*NHD];
__device__ float g_Wkh[ND*NHD];
__device__ float g_Wvh[ND*NHD];
__device__ float g_Wored[NHD*ND];
// pre-split bf16 planes of the weights
__device__ __nv_bfloat16 g_Wqh_hi[ND*NHD], g_Wqh_lo[ND*NHD];
__device__ __nv_bfloat16 g_Wkh_hi[ND*NHD], g_Wkh_lo[ND*NHD];
__device__ __nv_bfloat16 g_Wvh_hi[ND*NHD], g_Wvh_lo[ND*NHD];
__device__ __nv_bfloat16 g_Wo_hi[NHD*ND],  g_Wo_lo[NHD*ND];
// projected activations (bf16 planes)
__device__ __nv_bfloat16 g_qh_hi[NM*NHD], g_qh_lo[NM*NHD];
__device__ __nv_bfloat16 g_kh_hi[NM*NHD], g_kh_lo[NM*NHD];
__device__ __nv_bfloat16 g_vh_hi[NM*NHD], g_vh_lo[NM*NHD];
// split-KV attention partials
__device__ float g_po[2][NM*NHD];
__device__ float g_pm[2][NM];
__device__ float g_pl[2][NM];
// merged attention output (bf16 planes)
__device__ __nv_bfloat16 g_oh_hi[NM*NHD], g_oh_lo[NM*NHD];

// ---------------- helpers ---------------------------------------------------
__device__ __forceinline__ void bf16_split_pack(float x0, float x1,
                                                unsigned &hi, unsigned &lo) {
    __nv_bfloat16 h0 = __float2bfloat16_rn(x0);
    __nv_bfloat16 h1 = __float2bfloat16_rn(x1);
    __nv_bfloat16 l0 = __float2bfloat16_rn(x0 - __bfloat162float(h0));
    __nv_bfloat16 l1 = __float2bfloat16_rn(x1 - __bfloat162float(h1));
    hi = (unsigned)__bfloat16_as_ushort(h0) | ((unsigned)__bfloat16_as_ushort(h1) << 16);
    lo = (unsigned)__bfloat16_as_ushort(l0) | ((unsigned)__bfloat16_as_ushort(l1) << 16);
}
__device__ __forceinline__ void ldsm4(unsigned r[4], unsigned addr) {
    asm volatile("ldmatrix.sync.aligned.m8n8.x4.shared.b16 {%0,%1,%2,%3}, [%4];"
                 : "=r"(r[0]), "=r"(r[1]), "=r"(r[2]), "=r"(r[3]) : "r"(addr));
}
__device__ __forceinline__ void ldsm4t(unsigned r[4], unsigned addr) {
    asm volatile("ldmatrix.sync.aligned.m8n8.x4.trans.shared.b16 {%0,%1,%2,%3}, [%4];"
                 : "=r"(r[0]), "=r"(r[1]), "=r"(r[2]), "=r"(r[3]) : "r"(addr));
}
__device__ __forceinline__ void mma_bf16(float c[4], const unsigned a[4],
                                         unsigned b0, unsigned b1) {
    asm volatile(
        "mma.sync.aligned.m16n8k16.row.col.f32.bf16.bf16.f32 "
        "{%0,%1,%2,%3},{%4,%5,%6,%7},{%8,%9},{%0,%1,%2,%3};"
        : "+f"(c[0]), "+f"(c[1]), "+f"(c[2]), "+f"(c[3])
        : "r"(a[0]), "r"(a[1]), "r"(a[2]), "r"(a[3]), "r"(b0), "r"(b1));
}
__device__ __forceinline__ void cpa16(unsigned dst, const void* src) {
    asm volatile("cp.async.cg.shared.global [%0], [%1], 16;" :: "r"(dst), "l"(src));
}
#define CP_COMMIT asm volatile("cp.async.commit_group;")
#define CP_WAIT0  asm volatile("cp.async.wait_group 0;")
#define CP_WAIT1  asm volatile("cp.async.wait_group 1;")

// ---------------- tiny kernels ----------------------------------------------
__global__ void zero_wcomb_kernel() {
    int i = blockIdx.x*blockDim.x + threadIdx.x;
    if (i < ND*NHD) { g_Wqh[i]=0.f; g_Wkh[i]=0.f; g_Wvh[i]=0.f; }
}
__global__ void wored_kernel(const float* __restrict__ Wo) {
    int h = blockIdx.x;
    for (int e = threadIdx.x; e < ND; e += blockDim.x) {
        float s = 0.f;
        #pragma unroll
        for (int j = 0; j < 16; j++) s += Wo[(size_t)(j*NHD + h)*ND + e];
        g_Wored[h*ND + e] = s;
    }
}
// split the 4 combined f32 weight matrices into bf16 hi/lo planes
__global__ void wsplit_kernel() {
    int m = blockIdx.y;
    const float* src = (m==0)?g_Wqh:(m==1)?g_Wkh:(m==2)?g_Wvh:g_Wored;
    unsigned* hi = (unsigned*)((m==0)?g_Wqh_hi:(m==1)?g_Wkh_hi:(m==2)?g_Wvh_hi:g_Wo_hi);
    unsigned* lo = (unsigned*)((m==0)?g_Wqh_lo:(m==1)?g_Wkh_lo:(m==2)?g_Wvh_lo:g_Wo_lo);
    int i = blockIdx.x*blockDim.x + threadIdx.x;   // pair index < 32768
    float2 v = *(const float2*)(src + 2*i);
    unsigned h, l;
    bf16_split_pack(v.x, v.y, h, l);
    hi[i] = h; lo[i] = l;
}

// ---------------- combine: Wxh = Wx @ wx_h (f32 in, f32 atomic out) ---------
// M64xN64 core, BK=32, 256 thr, register-prefetch. split-K(8), grid (16,1,24)
#define G_SM_A_HI 0
#define G_SM_A_LO 5120
#define G_SM_B_HI 10240
#define G_SM_B_LO 14848
__global__ void __launch_bounds__(256) combine_kernel(
    const float* __restrict__ Wq, const float* __restrict__ Wk, const float* __restrict__ Wv,
    const float* __restrict__ wqh, const float* __restrict__ wkh, const float* __restrict__ wvh)
{
    int z = blockIdx.z;
    int which = z >> 3, chunk = z & 7;
    const float* A  = (which==0) ? Wq  : (which==1) ? Wk  : Wv;
    const float* Bm = (which==0) ? wqh : (which==1) ? wkh : wvh;
    float*       C  = (which==0) ? g_Wqh : (which==1) ? g_Wkh : g_Wvh;
    int m0 = blockIdx.x*64, kStart = chunk*128;

    __shared__ __align__(16) unsigned char sm[19456];
    unsigned sbase = (unsigned)__cvta_generic_to_shared(sm);
    int tid = threadIdx.x, lane = tid & 31, wid = tid >> 5;
    int wm = wid >> 1, wn = wid & 1;
    int lRow = lane & 15, lHi = (lane >> 4) << 3;

    float c[4][4] = {};
    float4 aReg[2], bReg[2];
    #pragma unroll
    for (int p = 0; p < 2; p++) {
        int idx = tid + p*256;
        aReg[p] = *(const float4*)(A + (size_t)(m0 + (idx>>3))*ND + kStart + (idx&7)*4);
        bReg[p] = *(const float4*)(Bm + (size_t)(kStart + (idx>>4))*NHD + (idx&15)*4);
    }
    for (int kb = 0; kb < 128; kb += 32) {
        #pragma unroll
        for (int p = 0; p < 2; p++) {
            int idx = tid + p*256;
            {   int r = idx>>3, c4 = idx&7;
                unsigned h01,l01,h23,l23;
                bf16_split_pack(aReg[p].x, aReg[p].y, h01, l01);
                bf16_split_pack(aReg[p].z, aReg[p].w, h23, l23);
                *(uint2*)(sm + G_SM_A_HI + r*80 + c4*8) = make_uint2(h01,h23);
                *(uint2*)(sm + G_SM_A_LO + r*80 + c4*8) = make_uint2(l01,l23);
            }
            {   int r = idx>>4, c4 = idx&15;
                unsigned h01,l01,h23,l23;
                bf16_split_pack(bReg[p].x, bReg[p].y, h01, l01);
                bf16_split_pack(bReg[p].z, bReg[p].w, h23, l23);
                *(uint2*)(sm + G_SM_B_HI + r*144 + c4*8) = make_uint2(h01,h23);
                *(uint2*)(sm + G_SM_B_LO + r*144 + c4*8) = make_uint2(l01,l23);
            }
        }
        __syncthreads();
        if (kb + 32 < 128) {
            int k0 = kStart + kb + 32;
            #pragma unroll
            for (int p = 0; p < 2; p++) {
                int idx = tid + p*256;
                aReg[p] = *(const float4*)(A + (size_t)(m0 + (idx>>3))*ND + k0 + (idx&7)*4);
                bReg[p] = *(const float4*)(Bm + (size_t)(k0 + (idx>>4))*NHD + (idx&15)*4);
            }
        }
        #pragma unroll
        for (int ks = 0; ks < 32; ks += 16) {
            unsigned ah[4], al[4], bh[2][4], bl[2][4];
            unsigned offA = sbase + G_SM_A_HI + (unsigned)((wm*16 + lRow)*80 + (ks + lHi)*2);
            ldsm4(ah, offA);
            ldsm4(al, offA + (G_SM_A_LO - G_SM_A_HI));
            #pragma unroll
            for (int np = 0; np < 2; np++) {
                unsigned offB = sbase + G_SM_B_HI + (unsigned)((ks + lRow)*144 + (wn*32 + np*16 + lHi)*2);
                ldsm4t(bh[np], offB);
                ldsm4t(bl[np], offB + (G_SM_B_LO - G_SM_B_HI));
            }
            #pragma unroll
            for (int nt = 0; nt < 4; nt++) {
                unsigned b0h = bh[nt>>1][(nt&1)*2], b1h = bh[nt>>1][(nt&1)*2+1];
                unsigned b0l = bl[nt>>1][(nt&1)*2], b1l = bl[nt>>1][(nt&1)*2+1];
                mma_bf16(c[nt], ah, b0h, b1h);
                mma_bf16(c[nt], ah, b0l, b1l);
                mma_bf16(c[nt], al, b0h, b1h);
            }
        }
        __syncthreads();
    }
    int rowL = m0 + wm*16 + (lane>>2);
    #pragma unroll
    for (int nt = 0; nt < 4; nt++) {
        int col = wn*32 + nt*8 + (lane&3)*2;
        atomicAdd(&C[(size_t)rowL*NHD+col],       c[nt][0]);
        atomicAdd(&C[(size_t)rowL*NHD+col+1],     c[nt][1]);
        atomicAdd(&C[(size_t)(rowL+8)*NHD+col],   c[nt][2]);
        atomicAdd(&C[(size_t)(rowL+8)*NHD+col+1], c[nt][3]);
    }
}

// ---------------- proj: xh = X @ Wxh + b, B pre-split, cp.async 2-stage -----
// M64 tile, N=64, K=1024. A: f32 register-prefetch + split. B: bf16 planes.
#define P_A_HI 0
#define P_A_LO 5120
#define P_BST(s) (10240 + (s)*9216)      // hi at +0, lo at +4608
__global__ void __launch_bounds__(256) proj_kernel(
    const float* __restrict__ q, const float* __restrict__ k, const float* __restrict__ v,
    const float* __restrict__ bq, const float* __restrict__ bk, const float* __restrict__ bv)
{
    int which = blockIdx.z;
    const float* A    = (which==0) ? q     : (which==1) ? k     : v;
    const __nv_bfloat16* Whi = (which==0) ? g_Wqh_hi : (which==1) ? g_Wkh_hi : g_Wvh_hi;
    const __nv_bfloat16* Wlo = (which==0) ? g_Wqh_lo : (which==1) ? g_Wkh_lo : g_Wvh_lo;
    const float* bias = (which==0) ? bq    : (which==1) ? bk    : bv;
    __nv_bfloat16* Chi = (which==0) ? g_qh_hi : (which==1) ? g_kh_hi : g_vh_hi;
    __nv_bfloat16* Clo = (which==0) ? g_qh_lo : (which==1) ? g_kh_lo : g_vh_lo;

    __shared__ __align__(16) unsigned char sm[28672];
    unsigned sbase = (unsigned)__cvta_generic_to_shared(sm);
    int tid = threadIdx.x, lane = tid & 31, wid = tid >> 5;
    int wm = wid >> 1, wn = wid & 1;
    int lRow = lane & 15, lHi = (lane >> 4) << 3;
    int m0 = blockIdx.x*64;

    float c[4][4] = {};
    // prologue: B stage0 + A regs
    #pragma unroll
    for (int p = 0; p < 2; p++) {
        int idx = tid + p*256;                       // 0..511
        int pl = idx >> 8, r = (idx >> 3) & 31, ch = idx & 7;
        const __nv_bfloat16* src = pl ? Wlo : Whi;
        cpa16(sbase + P_BST(0) + pl*4608 + r*144 + ch*16, src + (size_t)r*NHD + ch*8);
    }
    CP_COMMIT;
    float4 aReg[2];
    #pragma unroll
    for (int p = 0; p < 2; p++) {
        int idx = tid + p*256;
        aReg[p] = *(const float4*)(A + (size_t)(m0 + (idx>>3))*ND + (idx&7)*4);
    }

    for (int kb = 0, it = 0; kb < ND; kb += 32, it++) {
        int st = it & 1;
        __syncthreads();                    // prior mma finished with A smem / old B stage
        #pragma unroll
        for (int p = 0; p < 2; p++) {
            int idx = tid + p*256;
            int r = idx>>3, c4 = idx&7;
            unsigned h01,l01,h23,l23;
            bf16_split_pack(aReg[p].x, aReg[p].y, h01, l01);
            bf16_split_pack(aReg[p].z, aReg[p].w, h23, l23);
            *(uint2*)(sm + P_A_HI + r*80 + c4*8) = make_uint2(h01,h23);
            *(uint2*)(sm + P_A_LO + r*80 + c4*8) = make_uint2(l01,l23);
        }
        bool hasNext = (kb + 32 < ND);
        if (hasNext) {
            int k0 = kb + 32;
            #pragma unroll
            for (int p = 0; p < 2; p++) {
                int idx = tid + p*256;
                int pl = idx >> 8, r = (idx >> 3) & 31, ch = idx & 7;
                const __nv_bfloat16* src = pl ? Wlo : Whi;
                cpa16(sbase + P_BST(st^1) + pl*4608 + r*144 + ch*16,
                      src + (size_t)(k0 + r)*NHD + ch*8);
            }
        }
        CP_COMMIT;
        if (hasNext) {
            int k0 = kb + 32;
            #pragma unroll
            for (int p = 0; p < 2; p++) {
                int idx = tid + p*256;
                aReg[p] = *(const float4*)(A + (size_t)(m0 + (idx>>3))*ND + k0 + (idx&7)*4);
            }
        }
        CP_WAIT1;                           // current B stage resident
        __syncthreads();
        #pragma unroll
        for (int ks = 0; ks < 32; ks += 16) {
            unsigned ah[4], al[4], bh[2][4], bl[2][4];
            unsigned offA = sbase + P_A_HI + (unsigned)((wm*16 + lRow)*80 + (ks + lHi)*2);
            ldsm4(ah, offA);
            ldsm4(al, offA + (P_A_LO - P_A_HI));
            #pragma unroll
            for (int np = 0; np < 2; np++) {
                unsigned offB = sbase + P_BST(st) + (unsigned)((ks + lRow)*144 + (wn*32 + np*16 + lHi)*2);
                ldsm4t(bh[np], offB);
                ldsm4t(bl[np], offB + 4608);
            }
            #pragma unroll
            for (int nt = 0; nt < 4; nt++) {
                unsigned b0h = bh[nt>>1][(nt&1)*2], b1h = bh[nt>>1][(nt&1)*2+1];
                unsigned b0l = bl[nt>>1][(nt&1)*2], b1l = bl[nt>>1][(nt&1)*2+1];
                mma_bf16(c[nt], ah, b0h, b1h);
                mma_bf16(c[nt], ah, b0l, b1l);
                mma_bf16(c[nt], al, b0h, b1h);
            }
        }
    }
    int rowL = m0 + wm*16 + (lane>>2);
    #pragma unroll
    for (int nt = 0; nt < 4; nt++) {
        int col = wn*32 + nt*8 + (lane&3)*2;
        float v0 = c[nt][0] + bias[col],   v1 = c[nt][1] + bias[col+1];
        float v2 = c[nt][2] + bias[col],   v3 = c[nt][3] + bias[col+1];
        unsigned h01,l01,h23,l23;
        bf16_split_pack(v0,v1,h01,l01);
        bf16_split_pack(v2,v3,h23,l23);
        *(unsigned*)(Chi + (size_t)rowL*NHD + col)     = h01;
        *(unsigned*)(Clo + (size_t)rowL*NHD + col)     = l01;
        *(unsigned*)(Chi + (size_t)(rowL+8)*NHD + col) = h23;
        *(unsigned*)(Clo + (size_t)(rowL+8)*NHD + col) = l23;
    }
}

// ---------------- split-KV tensor-core causal flash attention ---------------
// BM=64, BN=32, 128 thr, grid (32 qtiles, 4 batch, 2 kv-splits).
// split 0: kv tiles [0, qb+1), split 1: [qb+1, 2qb+2). Partials to scratch.
#define AQ_HI 0
#define AQ_LO 8192
#define AST   16384
#define ASTSZ 16384

__device__ __forceinline__ void attn_load_stage(unsigned sbst, size_t kvbase, int tid) {
    #pragma unroll
    for (int p = 0; p < 2; p++) {
        int idx = tid + p*128;
        int r = idx >> 3, c = idx & 7;
        unsigned sw = (unsigned)(r*128 + ((c ^ (r & 7)) << 4));
        size_t g = kvbase + (size_t)r*NHD + c*8;
        cpa16(sbst + 0     + sw, g_kh_hi + g);
        cpa16(sbst + 4096  + sw, g_kh_lo + g);
        cpa16(sbst + 8192  + sw, g_vh_hi + g);
        cpa16(sbst + 12288 + sw, g_vh_lo + g);
    }
}

__global__ void __launch_bounds__(128) attn_kernel() {
    __shared__ __align__(16) unsigned char sm[49152];
    unsigned sb = (unsigned)__cvta_generic_to_shared(sm);
    int tid = threadIdx.x, lane = tid & 31, wid = tid >> 5;
    int qb = blockIdx.x, b = blockIdx.y, split = blockIdx.z;
    size_t base = (size_t)b * NS * NHD;
    int r0 = qb * 64;
    int jt0 = split ? (qb + 1) : 0;
    int jt1 = split ? (2*qb + 2) : (qb + 1);

    #pragma unroll
    for (int p = 0; p < 4; p++) {
        int idx = tid + p*128;
        int r = idx >> 3, c = idx & 7;
        unsigned sw = (unsigned)(r*128 + ((c ^ (r & 7)) << 4));
        size_t g = base + (size_t)(r0 + r)*NHD + c*8;
        cpa16(sb + AQ_HI + sw, g_qh_hi + g);
        cpa16(sb + AQ_LO + sw, g_qh_lo + g);
    }
    CP_COMMIT;
    attn_load_stage(sb + AST + (unsigned)((jt0 & 1) * ASTSZ), base + (size_t)jt0*32*NHD, tid);
    CP_COMMIT;
    CP_WAIT1;
    __syncthreads();

    unsigned qh_f[4][4], ql_f[4][4];
    {
        int row = wid*16 + (lane & 15);
        #pragma unroll
        for (int c = 0; c < 4; c++) {
            int ch = 2*c + (lane >> 4);
            unsigned addr = sb + AQ_HI + (unsigned)(row*128 + ((ch ^ (row & 7)) << 4));
            ldsm4(qh_f[c], addr);
            ldsm4(ql_f[c], addr + (AQ_LO - AQ_HI));
        }
    }

    float o[8][4] = {};
    float m0r = -1e30f, m1r = -1e30f, l0r = 0.f, l1r = 0.f;
    const float c1 = 0.125f * 1.4426950408889634f;

    for (int jt = jt0; jt < jt1; jt++) {
        unsigned cur = sb + AST + (unsigned)((jt & 1) * ASTSZ);
        if (jt + 1 < jt1)
            attn_load_stage(sb + AST + (unsigned)(((jt+1) & 1) * ASTSZ),
                            base + (size_t)(jt+1)*32*NHD, tid);
        CP_COMMIT;
        CP_WAIT1;
        __syncthreads();

        float s[4][4] = {};
        #pragma unroll
        for (int c = 0; c < 4; c++) {
            int ch = 2*c + ((lane >> 3) & 1);
            int keyr = ((lane >> 4) << 3) + (lane & 7);
            unsigned a0 = cur + (unsigned)(keyr*128 + ((ch ^ (keyr & 7)) << 4));
            unsigned a1 = a0 + 16*128;
            unsigned kh0[4], kh1[4], kl0[4], kl1[4];
            ldsm4(kh0, a0); ldsm4(kh1, a1);
            ldsm4(kl0, a0 + 4096); ldsm4(kl1, a1 + 4096);
            mma_bf16(s[0], qh_f[c], kh0[0], kh0[1]);
            mma_bf16(s[0], qh_f[c], kl0[0], kl0[1]);
            mma_bf16(s[0], ql_f[c], kh0[0], kh0[1]);
            mma_bf16(s[1], qh_f[c], kh0[2], kh0[3]);
            mma_bf16(s[1], qh_f[c], kl0[2], kl0[3]);
            mma_bf16(s[1], ql_f[c], kh0[2], kh0[3]);
            mma_bf16(s[2], qh_f[c], kh1[0], kh1[1]);
            mma_bf16(s[2], qh_f[c], kl1[0], kl1[1]);
            mma_bf16(s[2], ql_f[c], kh1[0], kh1[1]);
            mma_bf16(s[3], qh_f[c], kh1[2], kh1[3]);
            mma_bf16(s[3], qh_f[c], kl1[2], kl1[3]);
            mma_bf16(s[3], ql_f[c], kh1[2], kh1[3]);
        }

        bool dom = (jt >= 2*qb);
        int rgl = r0 + wid*16 + (lane >> 2);
        #pragma unroll
        for (int f = 0; f < 4; f++) {
            int kg = jt*32 + f*8 + (lane & 3)*2;
            #pragma unroll
            for (int e = 0; e < 4; e++) {
                float t = s[f][e] * c1;
                if (dom && (kg + (e & 1)) > (rgl + ((e >= 2) ? 8 : 0))) t = -1e30f;
                s[f][e] = t;
            }
        }

        float mx0 = -1e30f, mx1 = -1e30f;
        #pragma unroll
        for (int f = 0; f < 4; f++) {
            mx0 = fmaxf(mx0, fmaxf(s[f][0], s[f][1]));
            mx1 = fmaxf(mx1, fmaxf(s[f][2], s[f][3]));
        }
        mx0 = fmaxf(mx0, __shfl_xor_sync(0xffffffffu, mx0, 1));
        mx0 = fmaxf(mx0, __shfl_xor_sync(0xffffffffu, mx0, 2));
        mx1 = fmaxf(mx1, __shfl_xor_sync(0xffffffffu, mx1, 1));
        mx1 = fmaxf(mx1, __shfl_xor_sync(0xffffffffu, mx1, 2));
        float mn0 = fmaxf(m0r, mx0), mn1 = fmaxf(m1r, mx1);
        float al0 = exp2f(m0r - mn0), al1 = exp2f(m1r - mn1);
        m0r = mn0; m1r = mn1;
        float rs0 = 0.f, rs1 = 0.f;
        #pragma unroll
        for (int f = 0; f < 4; f++) {
            s[f][0] = exp2f(s[f][0] - mn0);
            s[f][1] = exp2f(s[f][1] - mn0);
            s[f][2] = exp2f(s[f][2] - mn1);
            s[f][3] = exp2f(s[f][3] - mn1);
            rs0 += s[f][0] + s[f][1];
            rs1 += s[f][2] + s[f][3];
        }
        rs0 += __shfl_xor_sync(0xffffffffu, rs0, 1);
        rs0 += __shfl_xor_sync(0xffffffffu, rs0, 2);
        rs1 += __shfl_xor_sync(0xffffffffu, rs1, 1);
        rs1 += __shfl_xor_sync(0xffffffffu, rs1, 2);
        l0r = l0r*al0 + rs0;
        l1r = l1r*al1 + rs1;
        #pragma unroll
        for (int f = 0; f < 8; f++) {
            o[f][0] *= al0; o[f][1] *= al0;
            o[f][2] *= al1; o[f][3] *= al1;
        }

        #pragma unroll
        for (int ka = 0; ka < 2; ka++) {
            unsigned ph[4], pl[4];
            bf16_split_pack(s[2*ka][0],   s[2*ka][1],   ph[0], pl[0]);
            bf16_split_pack(s[2*ka][2],   s[2*ka][3],   ph[1], pl[1]);
            bf16_split_pack(s[2*ka+1][0], s[2*ka+1][1], ph[2], pl[2]);
            bf16_split_pack(s[2*ka+1][2], s[2*ka+1][3], ph[3], pl[3]);
            #pragma unroll
            for (int fp = 0; fp < 4; fp++) {
                int ch = 2*fp + (lane >> 4);
                int kvr = ka*16 + (lane & 15);
                unsigned av = cur + 8192 + (unsigned)(kvr*128 + ((ch ^ (kvr & 7)) << 4));
                unsigned vh[4], vl[4];
                ldsm4t(vh, av); ldsm4t(vl, av + 4096);
                mma_bf16(o[2*fp],   ph, vh[0], vh[1]);
                mma_bf16(o[2*fp],   pl, vh[0], vh[1]);
                mma_bf16(o[2*fp],   ph, vl[0], vl[1]);
                mma_bf16(o[2*fp+1], ph, vh[2], vh[3]);
                mma_bf16(o[2*fp+1], pl, vh[2], vh[3]);
                mma_bf16(o[2*fp+1], ph, vl[2], vl[3]);
            }
        }
        __syncthreads();
    }

    // partial epilogue: unnormalized O + stats
    int rowg = r0 + wid*16 + (lane >> 2);
    size_t rb = (size_t)b*NS + rowg;
    #pragma unroll
    for (int f = 0; f < 8; f++) {
        int hd = f*8 + (lane & 3)*2;
        *(float2*)(g_po[split] + rb*NHD + hd)     = make_float2(o[f][0], o[f][1]);
        *(float2*)(g_po[split] + (rb+8)*NHD + hd) = make_float2(o[f][2], o[f][3]);
    }
    if ((lane & 3) == 0) {
        g_pm[split][rb]   = m0r;  g_pl[split][rb]   = l0r;
        g_pm[split][rb+8] = m1r;  g_pl[split][rb+8] = l1r;
    }
}

// ---------------- merge split-KV partials -> bf16 hi/lo planes --------------
__global__ void merge_kernel() {
    int idx = blockIdx.x*blockDim.x + threadIdx.x;    // 0 .. NM*32-1
    int row = idx >> 5;
    int cp  = (idx & 31)*2;
    float m0 = g_pm[0][row], m1 = g_pm[1][row];
    float M = fmaxf(m0, m1);
    float e0 = exp2f(m0 - M), e1 = exp2f(m1 - M);
    float inv = 1.f / (g_pl[0][row]*e0 + g_pl[1][row]*e1);
    float2 a = *(const float2*)(g_po[0] + (size_t)row*NHD + cp);
    float2 bv = *(const float2*)(g_po[1] + (size_t)row*NHD + cp);
    float x0 = (a.x*e0 + bv.x*e1)*inv;
    float x1 = (a.y*e0 + bv.y*e1)*inv;
    unsigned h, l;
    bf16_split_pack(x0, x1, h, l);
    *(unsigned*)(g_oh_hi + (size_t)row*NHD + cp) = h;
    *(unsigned*)(g_oh_lo + (size_t)row*NHD + cp) = l;
}

// ---------------- outgemm: out = oh @ Wo_red (all-bf16, single K=64 shot) ---
#define O_A_HI 0
#define O_A_LO 9216
#define O_B_HI 18432
#define O_B_LO 27648
__global__ void __launch_bounds__(256) outgemm_kernel(float* __restrict__ out) {
    __shared__ __align__(16) unsigned char sm[36864];
    unsigned sbase = (unsigned)__cvta_generic_to_shared(sm);
    int tid = threadIdx.x, lane = tid & 31, wid = tid >> 5;
    int wm = wid >> 1, wn = wid & 1;
    int lRow = lane & 15, lHi = (lane >> 4) << 3;
    int m0 = blockIdx.x*64, n0 = blockIdx.y*64;

    // A: oh planes [8192x64]; B: Wored planes [64x1024] (n-slice)
    #pragma unroll
    for (int p = 0; p < 4; p++) {
        int idx = tid + p*256;                 // 0..1023
        int pl = (idx >> 9) & 1, r = (idx >> 3) & 63, ch = idx & 7;
        if (idx < 1024) {
            const __nv_bfloat16* srcA = pl ? g_oh_lo : g_oh_hi;
            cpa16(sbase + O_A_HI + pl*9216 + r*144 + ch*16, srcA + (size_t)(m0 + r)*NHD + ch*8);
        }
    }
    #pragma unroll
    for (int p = 0; p < 4; p++) {
        int idx = tid + p*256;
        int pl = (idx >> 9) & 1, r = (idx >> 3) & 63, ch = idx & 7;
        const __nv_bfloat16* srcB = pl ? g_Wo_lo : g_Wo_hi;
        cpa16(sbase + O_B_HI + pl*9216 + r*144 + ch*16, srcB + (size_t)r*ND + n0 + ch*8);
    }
    CP_COMMIT;
    CP_WAIT0;
    __syncthreads();

    float c[4][4] = {};
    #pragma unroll
    for (int ks = 0; ks < 4; ks++) {
        unsigned ah[4], al[4], bh[2][4], bl[2][4];
        unsigned offA = sbase + O_A_HI + (unsigned)((wm*16 + lRow)*144 + (ks*16 + lHi)*2);
        ldsm4(ah, offA);
        ldsm4(al, offA + 9216);
        #pragma unroll
        for (int np = 0; np < 2; np++) {
            unsigned offB = sbase + O_B_HI + (unsigned)((ks*16 + lRow)*144 + (wn*32 + np*16 + lHi)*2);
            ldsm4t(bh[np], offB);
            ldsm4t(bl[np], offB + 9216);
        }
        #pragma unroll
        for (int nt = 0; nt < 4; nt++) {
            unsigned b0h = bh[nt>>1][(nt&1)*2], b1h = bh[nt>>1][(nt&1)*2+1];
            unsigned b0l = bl[nt>>1][(nt&1)*2], b1l = bl[nt>>1][(nt&1)*2+1];
            mma_bf16(c[nt], ah, b0h, b1h);
            mma_bf16(c[nt], ah, b0l, b1l);
            mma_bf16(c[nt], al, b0h, b1h);
        }
    }
    int rowL = m0 + wm*16 + (lane>>2);
    #pragma unroll
    for (int nt = 0; nt < 4; nt++) {
        int col = n0 + wn*32 + nt*8 + (lane&3)*2;
        *(float2*)(out + (size_t)rowL*ND + col)     = make_float2(c[nt][0], c[nt][1]);
        *(float2*)(out + (size_t)(rowL+8)*ND + col) = make_float2(c[nt][2], c[nt][3]);
    }
}

// ---------------- launch ----------------------------------------------------
extern "C" void kernel_launch(void* const* d_in, const int* in_sizes, int n_in,
                              void* d_out, int out_size) {
    const float* query = (const float*)d_in[0];
    const float* key   = (const float*)d_in[1];
    const float* value = (const float*)d_in[2];
    // d_in[3] = mask (causal, reconstructed analytically — unused)
    const float* Wq   = (const float*)d_in[4];
    const float* Wk   = (const float*)d_in[5];
    const float* Wv   = (const float*)d_in[6];
    const float* wq_h = (const float*)d_in[7];
    const float* bq_h = (const float*)d_in[8];
    const float* wk_h = (const float*)d_in[9];
    const float* bk_h = (const float*)d_in[10];
    const float* wv_h = (const float*)d_in[11];
    const float* bv_h = (const float*)d_in[12];
    const float* Wo   = (const float*)d_in[13];
    float* out = (float*)d_out;

    zero_wcomb_kernel<<<(ND*NHD + 255)/256, 256>>>();
    wored_kernel<<<NHD, 256>>>(Wo);
    combine_kernel<<<dim3(16, 1, 24), 256>>>(Wq, Wk, Wv, wq_h, wk_h, wv_h);
    wsplit_kernel<<<dim3(128, 4), 256>>>();
    proj_kernel<<<dim3(128, 1, 3), 256>>>(query, key, value, bq_h, bk_h, bv_h);
    attn_kernel<<<dim3(32, NB, 2), 128>>>();
    merge_kernel<<<NM*32/256, 256>>>();
    outgemm_kernel<<<dim3(128, 16), 256>>>(out);
}